// round 1
// baseline (speedup 1.0000x reference)
#include <cuda_runtime.h>
#include <cuda_bf16.h>
#include <math_constants.h>

// Problem constants (fixed by the reference)
#define BB    2
#define LL    1024
#define DD    1024
#define HH    16
#define HD    64
#define NTOK  2048          // B*L
#define FFN   2048
#define QSCALE 0.125f       // 1/sqrt(64)

// ---------------- scratch (static device globals; no allocation) ----------
__device__ float g_q   [NTOK * DD];              // [tok][D] (pre-scaled by 1/8)
__device__ float g_kt  [BB * DD * LL];           // [b][h*64+d][k]  (K transposed)
__device__ float g_v   [NTOK * DD];              // [tok][D]
__device__ float g_gate[NTOK * DD];              // sigmoid(x@wg+bg)
__device__ float g_s   [(size_t)BB * HH * LL * LL]; // [b][h][q][k] bias->scores->probs
__device__ float g_o   [NTOK * DD];              // gated attention output
__device__ float g_r1  [NTOK * DD];
__device__ float g_y   [NTOK * DD];
__device__ float g_u   [NTOK * FFN];
__device__ float g_r2  [NTOK * DD];

// ---------------- generic tiled SGEMM with epilogues ----------------------
enum { EPI_SCALE = 0, EPI_KT = 1, EPI_SIGB = 2, EPI_BIASADD_MASK = 3,
       EPI_GATE = 4, EPI_RESBIAS = 5, EPI_SILU = 6 };

template<int EPI>
__global__ __launch_bounds__(256)
void sgemm(const float* __restrict__ A, const float* __restrict__ B,
           float* __restrict__ C,
           int M, int N, int K, int lda, int ldb, int ldc,
           int zdiv,
           long long sA1, long long sA2,
           long long sB1, long long sB2,
           long long sC1, long long sC2,
           const float* __restrict__ bias,
           const float* __restrict__ res,
           const unsigned char* __restrict__ mask,
           float scale)
{
    int z  = blockIdx.z;
    int z1 = z / zdiv;
    int z2 = z % zdiv;
    A += (size_t)z1 * sA1 + (size_t)z2 * sA2;
    B += (size_t)z1 * sB1 + (size_t)z2 * sB2;
    size_t coff = (size_t)z1 * sC1 + (size_t)z2 * sC2;

    __shared__ float As[8][128];
    __shared__ float Bs[8][132];

    int tid  = threadIdx.x;
    int arow = tid >> 1;
    int acol = (tid & 1) * 4;
    int brow = tid >> 5;
    int bcol = (tid & 31) * 4;
    int tx   = tid & 15;
    int ty   = tid >> 4;

    const float* Ap = A + (size_t)(blockIdx.y * 128 + arow) * lda + acol;
    int nB = blockIdx.x * 128 + bcol;
    const float* Bp = B + (size_t)brow * ldb + nB;
    bool bvalid = nB < N;

    float acc[8][8];
#pragma unroll
    for (int i = 0; i < 8; i++)
#pragma unroll
        for (int j = 0; j < 8; j++) acc[i][j] = 0.f;

    for (int k0 = 0; k0 < K; k0 += 8) {
        float4 av = *(const float4*)(Ap + k0);
        float4 bv = bvalid ? *(const float4*)(Bp + (size_t)k0 * ldb)
                           : make_float4(0.f, 0.f, 0.f, 0.f);
        As[acol + 0][arow] = av.x;
        As[acol + 1][arow] = av.y;
        As[acol + 2][arow] = av.z;
        As[acol + 3][arow] = av.w;
        *(float4*)&Bs[brow][bcol] = bv;
        __syncthreads();
#pragma unroll
        for (int kk = 0; kk < 8; kk++) {
            float ar[8], br[8];
            *(float4*)(ar)     = *(const float4*)&As[kk][ty * 8];
            *(float4*)(ar + 4) = *(const float4*)&As[kk][ty * 8 + 4];
            *(float4*)(br)     = *(const float4*)&Bs[kk][tx * 8];
            *(float4*)(br + 4) = *(const float4*)&Bs[kk][tx * 8 + 4];
#pragma unroll
            for (int i = 0; i < 8; i++)
#pragma unroll
                for (int j = 0; j < 8; j++)
                    acc[i][j] = fmaf(ar[i], br[j], acc[i][j]);
        }
        __syncthreads();
    }

    int m0 = blockIdx.y * 128 + ty * 8;
    int n0 = blockIdx.x * 128 + tx * 8;
#pragma unroll
    for (int i = 0; i < 8; i++) {
        int m = m0 + i;
#pragma unroll
        for (int j = 0; j < 8; j++) {
            int n = n0 + j;
            if (n >= N) continue;
            float v = acc[i][j];
            size_t idx = coff + (size_t)m * ldc + n;
            if (EPI == EPI_SCALE) {
                C[idx] = v * scale;
            } else if (EPI == EPI_KT) {
                // token m = b*1024 + k ; column n = h*64+d  ->  kt[b][n][k]
                size_t o = (size_t)(m >> 10) * (1u << 20) + (size_t)n * 1024 + (m & 1023);
                C[o] = v;
            } else if (EPI == EPI_SIGB) {
                float zz = v + bias[n];
                C[idx] = 1.f / (1.f + __expf(-zz));
            } else if (EPI == EPI_BIASADD_MASK) {
                float t = v + C[idx];                 // C preloaded with bias
                if (mask && mask[z1 * 1024 + n]) t = -CUDART_INF_F;
                C[idx] = t;
            } else if (EPI == EPI_GATE) {
                C[idx] = v * res[idx];
            } else if (EPI == EPI_RESBIAS) {
                C[idx] = v + bias[n] + res[idx];
            } else if (EPI == EPI_SILU) {
                float zz = v + bias[n];
                C[idx] = zz / (1.f + __expf(-zz));
            }
        }
    }
}

// ---------------- edge_bias [b,q,k,h] -> g_s [b,h,q,k] ---------------------
__global__ void bias_transpose(const float* __restrict__ eb, float* __restrict__ s)
{
    int kc = blockIdx.x;          // 64-wide k chunk
    int q  = blockIdx.y;
    int b  = blockIdx.z;
    __shared__ float t[64 * 17];
    size_t ibase = (((size_t)(b * 1024 + q)) * 1024 + kc * 64) * 16;
    for (int idx = threadIdx.x; idx < 1024; idx += 256)
        t[(idx >> 4) * 17 + (idx & 15)] = eb[ibase + idx];
    __syncthreads();
    for (int idx = threadIdx.x; idx < 1024; idx += 256) {
        int h = idx >> 6, kk = idx & 63;
        s[(((size_t)(b * 16 + h) * 1024 + q)) * 1024 + kc * 64 + kk] = t[kk * 17 + h];
    }
}

// ------- softmax over k: rows of g_s [b,h,q,:]; also emit d_out [b,q,k,h] --
__global__ __launch_bounds__(512)
void softmax_kernel(float* __restrict__ s, float* __restrict__ attn_out)
{
    int q = blockIdx.x;
    int b = blockIdx.y;
    int w    = threadIdx.x >> 5;   // head
    int lane = threadIdx.x & 31;
    float* row = s + (((size_t)(b * 16 + w) * 1024 + q)) * 1024;

    float v[32];
    float mx = -CUDART_INF_F;
#pragma unroll
    for (int i = 0; i < 32; i++) {
        v[i] = row[i * 32 + lane];
        mx = fmaxf(mx, v[i]);
    }
#pragma unroll
    for (int o = 16; o; o >>= 1) mx = fmaxf(mx, __shfl_xor_sync(0xffffffffu, mx, o));
    float sum = 0.f;
#pragma unroll
    for (int i = 0; i < 32; i++) { v[i] = __expf(v[i] - mx); sum += v[i]; }
#pragma unroll
    for (int o = 16; o; o >>= 1) sum += __shfl_xor_sync(0xffffffffu, sum, o);
    float inv = 1.f / sum;
#pragma unroll
    for (int i = 0; i < 32; i++) { v[i] *= inv; row[i * 32 + lane] = v[i]; }

    // transpose-stage into [k,h] order for coalesced d_out writes
    __shared__ float tile[16 * 513];
    float* out = attn_out + ((size_t)(b * 1024 + q)) * 16384;
#pragma unroll
    for (int half = 0; half < 2; half++) {
        __syncthreads();
#pragma unroll
        for (int i = 0; i < 16; i++) {
            int k = (half * 16 + i) * 32 + lane;
            tile[w * 513 + (k - half * 512)] = v[half * 16 + i];
        }
        __syncthreads();
        for (int idx = threadIdx.x; idx < 8192; idx += 512) {
            int k = idx >> 4, h = idx & 15;
            out[half * 8192 + idx] = tile[h * 513 + k];
        }
    }
}

// ---------------- row LayerNorm over D=1024 --------------------------------
__global__ __launch_bounds__(256)
void ln_kernel(const float* __restrict__ in, float* __restrict__ out,
               const float* __restrict__ gg, const float* __restrict__ bb)
{
    int row = blockIdx.x;
    int tid = threadIdx.x;
    float4 v = reinterpret_cast<const float4*>(in + (size_t)row * 1024)[tid];
    float s  = v.x + v.y + v.z + v.w;
    float ss = v.x * v.x + v.y * v.y + v.z * v.z + v.w * v.w;
#pragma unroll
    for (int o = 16; o; o >>= 1) {
        s  += __shfl_xor_sync(0xffffffffu, s, o);
        ss += __shfl_xor_sync(0xffffffffu, ss, o);
    }
    __shared__ float rs[8], rss[8];
    if ((tid & 31) == 0) { rs[tid >> 5] = s; rss[tid >> 5] = ss; }
    __syncthreads();
    if (tid < 32) {
        float a = (tid < 8) ? rs[tid] : 0.f;
        float c = (tid < 8) ? rss[tid] : 0.f;
#pragma unroll
        for (int o = 4; o; o >>= 1) {
            a += __shfl_xor_sync(0xffffffffu, a, o);
            c += __shfl_xor_sync(0xffffffffu, c, o);
        }
        if (tid == 0) { rs[0] = a; rss[0] = c; }
    }
    __syncthreads();
    float mean = rs[0] * (1.f / 1024.f);
    float var  = rss[0] * (1.f / 1024.f) - mean * mean;
    float inv  = rsqrtf(var + 1e-5f);
    float4 g4 = ((const float4*)gg)[tid];
    float4 b4 = ((const float4*)bb)[tid];
    float4 o4;
    o4.x = (v.x - mean) * inv * g4.x + b4.x;
    o4.y = (v.y - mean) * inv * g4.y + b4.y;
    o4.z = (v.z - mean) * inv * g4.z + b4.z;
    o4.w = (v.w - mean) * inv * g4.w + b4.w;
    reinterpret_cast<float4*>(out + (size_t)row * 1024)[tid] = o4;
}

// ---------------- launcher --------------------------------------------------
extern "C" void kernel_launch(void* const* d_in, const int* in_sizes, int n_in,
                              void* d_out, int out_size)
{
    const float* x    = (const float*)d_in[0];
    const float* eb   = (const float*)d_in[1];
    const unsigned char* mask = (const unsigned char*)d_in[2];
    const float* wq   = (const float*)d_in[3];
    const float* wk   = (const float*)d_in[4];
    const float* wv   = (const float*)d_in[5];
    const float* wo   = (const float*)d_in[6];
    const float* bo   = (const float*)d_in[7];
    const float* wg   = (const float*)d_in[8];
    const float* bg   = (const float*)d_in[9];
    const float* w1   = (const float*)d_in[10];
    const float* b1   = (const float*)d_in[11];
    const float* w2   = (const float*)d_in[12];
    const float* b2   = (const float*)d_in[13];
    const float* ln1g = (const float*)d_in[14];
    const float* ln1b = (const float*)d_in[15];
    const float* ln2g = (const float*)d_in[16];
    const float* ln2b = (const float*)d_in[17];

    float* out_x    = (float*)d_out;
    float* out_attn = (float*)d_out + (size_t)NTOK * 1024; // 2M floats of x first

    float *q, *kt, *v, *g, *s, *o, *r1, *y, *u, *r2;
    cudaGetSymbolAddress((void**)&q,  g_q);
    cudaGetSymbolAddress((void**)&kt, g_kt);
    cudaGetSymbolAddress((void**)&v,  g_v);
    cudaGetSymbolAddress((void**)&g,  g_gate);
    cudaGetSymbolAddress((void**)&s,  g_s);
    cudaGetSymbolAddress((void**)&o,  g_o);
    cudaGetSymbolAddress((void**)&r1, g_r1);
    cudaGetSymbolAddress((void**)&y,  g_y);
    cudaGetSymbolAddress((void**)&u,  g_u);
    cudaGetSymbolAddress((void**)&r2, g_r2);

    dim3 blk(256);

    // 1) edge_bias -> g_s ([b,h,q,k])
    bias_transpose<<<dim3(16, 1024, 2), 256>>>(eb, s);

    // 2) projections
    sgemm<EPI_SCALE><<<dim3(8, 16, 1), blk>>>(x, wq, q, NTOK, 1024, 1024, 1024, 1024, 1024,
        1, 0, 0, 0, 0, 0, 0, nullptr, nullptr, nullptr, QSCALE);
    sgemm<EPI_KT><<<dim3(8, 16, 1), blk>>>(x, wk, kt, NTOK, 1024, 1024, 1024, 1024, 1024,
        1, 0, 0, 0, 0, 0, 0, nullptr, nullptr, nullptr, 1.f);
    sgemm<EPI_SCALE><<<dim3(8, 16, 1), blk>>>(x, wv, v, NTOK, 1024, 1024, 1024, 1024, 1024,
        1, 0, 0, 0, 0, 0, 0, nullptr, nullptr, nullptr, 1.f);
    sgemm<EPI_SIGB><<<dim3(8, 16, 1), blk>>>(x, wg, g, NTOK, 1024, 1024, 1024, 1024, 1024,
        1, 0, 0, 0, 0, 0, 0, bg, nullptr, nullptr, 1.f);

    // 3) scores: per (b,h): Q_h[1024,64] @ Kt_h[64,1024] + bias (+mask), into g_s
    sgemm<EPI_BIASADD_MASK><<<dim3(8, 8, 32), blk>>>(q, kt, s, 1024, 1024, 64,
        1024, 1024, 1024,
        16,
        (long long)1048576, 64,           // A: b*L*D, h*64
        (long long)1048576, 65536,        // B: b*D*L, (h*64)*1024
        (long long)16777216, 1048576,     // C: b*16M,  h*1M
        nullptr, nullptr, mask, 1.f);

    // 4) softmax over keys; probs back to g_s, and to d_out [b,q,k,h]
    softmax_kernel<<<dim3(1024, 2), 512>>>(s, out_attn);

    // 5) o = (probs @ V_h) * gate
    sgemm<EPI_GATE><<<dim3(1, 8, 32), blk>>>(s, v, o, 1024, 64, 1024,
        1024, 1024, 1024,
        16,
        (long long)16777216, 1048576,     // A: probs
        (long long)1048576, 64,           // B: V_h
        (long long)1048576, 64,           // C: o
        nullptr, g, nullptr, 1.f);

    // 6) delta = o @ wo + bo + x  -> r1 ; LN1 -> y
    sgemm<EPI_RESBIAS><<<dim3(8, 16, 1), blk>>>(o, wo, r1, NTOK, 1024, 1024, 1024, 1024, 1024,
        1, 0, 0, 0, 0, 0, 0, bo, x, nullptr, 1.f);
    ln_kernel<<<NTOK, 256>>>(r1, y, ln1g, ln1b);

    // 7) FFN: silu(y@w1+b1) @ w2 + b2 + y -> r2 ; LN2 -> out_x
    sgemm<EPI_SILU><<<dim3(16, 16, 1), blk>>>(y, w1, u, NTOK, FFN, 1024, 1024, FFN, FFN,
        1, 0, 0, 0, 0, 0, 0, b1, nullptr, nullptr, 1.f);
    sgemm<EPI_RESBIAS><<<dim3(8, 16, 1), blk>>>(u, w2, r2, NTOK, 1024, FFN, FFN, 1024, 1024,
        1, 0, 0, 0, 0, 0, 0, b2, y, nullptr, 1.f);
    ln_kernel<<<NTOK, 256>>>(r2, out_x, ln2g, ln2b);
}

// round 2
// speedup vs baseline: 2.8345x; 2.8345x over previous
#include <cuda_runtime.h>
#include <cuda_bf16.h>
#include <math_constants.h>

#define BB    2
#define LL    1024
#define DD    1024
#define HH    16
#define HD    64
#define NTOK  2048
#define FFN   2048
#define QSCALE 0.125f

// ---------------- scratch ----------------
__device__ float g_q   [NTOK * DD];
__device__ float g_kt  [BB * DD * LL];
__device__ float g_v   [NTOK * DD];
__device__ float g_gate[NTOK * DD];
__device__ float g_s   [(size_t)BB * HH * LL * LL];
__device__ float g_o   [NTOK * DD];
__device__ float g_r1  [NTOK * DD];
__device__ float g_y   [NTOK * DD];
__device__ float g_u   [NTOK * FFN];
__device__ float g_r2  [NTOK * DD];

enum { EPI_SCALE = 0, EPI_KT = 1, EPI_SIGB = 2, EPI_BIASADD_MASK = 3,
       EPI_GATE = 4, EPI_RESBIAS = 5, EPI_SILU = 6 };

__device__ __forceinline__ unsigned f2tf32(float f) {
    unsigned r;
    asm("cvt.rna.tf32.f32 %0, %1;" : "=r"(r) : "f"(f));
    return r;
}

__device__ __forceinline__ void cp16(unsigned dst, const void* src, bool pred) {
    int sz = pred ? 16 : 0;
    asm volatile("cp.async.cg.shared.global [%0], [%1], 16, %2;"
                 :: "r"(dst), "l"(src), "r"(sz));
}

__device__ __forceinline__ void mma_tf32(float* c, const unsigned* a, const unsigned* b) {
    asm volatile(
        "mma.sync.aligned.m16n8k8.row.col.f32.tf32.tf32.f32 "
        "{%0,%1,%2,%3}, {%4,%5,%6,%7}, {%8,%9}, {%0,%1,%2,%3};"
        : "+f"(c[0]), "+f"(c[1]), "+f"(c[2]), "+f"(c[3])
        : "r"(a[0]), "r"(a[1]), "r"(a[2]), "r"(a[3]), "r"(b[0]), "r"(b[1]));
}

// ------------- TF32 tensor-core GEMM, 128x128 tile, BK=16, epilogues -------
#define AS_STRIDE 20
#define BS_STRIDE 136

template<int EPI>
__global__ __launch_bounds__(256)
void tgemm(const float* __restrict__ A, const float* __restrict__ B,
           float* __restrict__ C,
           int M, int N, int K, int lda, int ldb, int ldc,
           int zdiv,
           long long sA1, long long sA2,
           long long sB1, long long sB2,
           long long sC1, long long sC2,
           const float* __restrict__ bias,
           const float* __restrict__ res,
           const unsigned char* __restrict__ mask,
           float scale)
{
    __shared__ float As[2][128 * AS_STRIDE];
    __shared__ float Bs[2][16 * BS_STRIDE];

    int z  = blockIdx.z;
    int z1 = z / zdiv;
    int z2 = z % zdiv;
    A += (size_t)z1 * sA1 + (size_t)z2 * sA2;
    B += (size_t)z1 * sB1 + (size_t)z2 * sB2;
    size_t coff = (size_t)z1 * sC1 + (size_t)z2 * sC2;

    int tid  = threadIdx.x;
    int lane = tid & 31;
    int wid  = tid >> 5;
    int wm   = (wid & 3) * 32;     // warp m offset in tile
    int wn   = (wid >> 2) * 64;    // warp n offset in tile
    int bm   = blockIdx.y;
    int bn   = blockIdx.x;

    unsigned as_base = (unsigned)__cvta_generic_to_shared(As);
    unsigned bs_base = (unsigned)__cvta_generic_to_shared(Bs);

    const float* Ag = A + (size_t)(bm * 128) * lda;
    const float* Bg = B + bn * 128;

    float acc[2][8][4];
#pragma unroll
    for (int i = 0; i < 2; i++)
#pragma unroll
        for (int j = 0; j < 8; j++)
#pragma unroll
            for (int r = 0; r < 4; r++) acc[i][j][r] = 0.f;

    int KT = K >> 4;

    // prologue: stage 0
    {
#pragma unroll
        for (int i = 0; i < 2; i++) {
            int f = tid + 256 * i;
            int row = f >> 2, c4 = f & 3;
            cp16(as_base + (unsigned)(row * AS_STRIDE + c4 * 4) * 4,
                 Ag + (size_t)row * lda + c4 * 4, true);
        }
#pragma unroll
        for (int i = 0; i < 2; i++) {
            int f = tid + 256 * i;
            int row = f >> 5, c4 = f & 31;
            int col = bn * 128 + c4 * 4;
            cp16(bs_base + (unsigned)(row * BS_STRIDE + c4 * 4) * 4,
                 Bg + (size_t)row * ldb + c4 * 4, col < N);
        }
        asm volatile("cp.async.commit_group;");
    }

    for (int kt = 0; kt < KT; kt++) {
        int st = kt & 1;
        if (kt + 1 < KT) {
            int ns = st ^ 1;
            int k0 = (kt + 1) * 16;
#pragma unroll
            for (int i = 0; i < 2; i++) {
                int f = tid + 256 * i;
                int row = f >> 2, c4 = f & 3;
                cp16(as_base + (unsigned)(ns * 128 * AS_STRIDE + row * AS_STRIDE + c4 * 4) * 4,
                     Ag + (size_t)row * lda + k0 + c4 * 4, true);
            }
#pragma unroll
            for (int i = 0; i < 2; i++) {
                int f = tid + 256 * i;
                int row = f >> 5, c4 = f & 31;
                int col = bn * 128 + c4 * 4;
                cp16(bs_base + (unsigned)(ns * 16 * BS_STRIDE + row * BS_STRIDE + c4 * 4) * 4,
                     Bg + (size_t)(k0 + row) * ldb + c4 * 4, col < N);
            }
            asm volatile("cp.async.commit_group;");
            asm volatile("cp.async.wait_group %0;" :: "n"(1));
        } else {
            asm volatile("cp.async.wait_group %0;" :: "n"(0));
        }
        __syncthreads();

        const float* As_ = As[st];
        const float* Bs_ = Bs[st];
#pragma unroll
        for (int kk = 0; kk < 16; kk += 8) {
            unsigned a[2][4], b[8][2];
            int ar = lane >> 2;
            int ac = kk + (lane & 3);
#pragma unroll
            for (int mt = 0; mt < 2; mt++) {
                int r = wm + mt * 16 + ar;
                a[mt][0] = f2tf32(As_[r * AS_STRIDE + ac]);
                a[mt][1] = f2tf32(As_[(r + 8) * AS_STRIDE + ac]);
                a[mt][2] = f2tf32(As_[r * AS_STRIDE + ac + 4]);
                a[mt][3] = f2tf32(As_[(r + 8) * AS_STRIDE + ac + 4]);
            }
            int br = kk + (lane & 3);
            int bc = wn + (lane >> 2);
#pragma unroll
            for (int nt = 0; nt < 8; nt++) {
                b[nt][0] = f2tf32(Bs_[br * BS_STRIDE + bc + nt * 8]);
                b[nt][1] = f2tf32(Bs_[(br + 4) * BS_STRIDE + bc + nt * 8]);
            }
#pragma unroll
            for (int mt = 0; mt < 2; mt++)
#pragma unroll
                for (int nt = 0; nt < 8; nt++)
                    mma_tf32(acc[mt][nt], a[mt], b[nt]);
        }
        __syncthreads();
    }

    // epilogue
#pragma unroll
    for (int mt = 0; mt < 2; mt++) {
        int r0 = bm * 128 + wm + mt * 16 + (lane >> 2);
#pragma unroll
        for (int nt = 0; nt < 8; nt++) {
            int c0 = bn * 128 + wn + nt * 8 + (lane & 3) * 2;
#pragma unroll
            for (int e = 0; e < 4; e++) {
                int m = r0 + (e >> 1) * 8;
                int n = c0 + (e & 1);
                if (n >= N) continue;
                float v = acc[mt][nt][e];
                size_t idx = coff + (size_t)m * ldc + n;
                if (EPI == EPI_SCALE) {
                    C[idx] = v * scale;
                } else if (EPI == EPI_KT) {
                    size_t o = (size_t)(m >> 10) * (1u << 20) + (size_t)n * 1024 + (m & 1023);
                    C[o] = v;
                } else if (EPI == EPI_SIGB) {
                    float zz = v + bias[n];
                    C[idx] = 1.f / (1.f + __expf(-zz));
                } else if (EPI == EPI_BIASADD_MASK) {
                    float t = v + C[idx];
                    if (mask && mask[z1 * 1024 + n]) t = -CUDART_INF_F;
                    C[idx] = t;
                } else if (EPI == EPI_GATE) {
                    C[idx] = v * res[idx];
                } else if (EPI == EPI_RESBIAS) {
                    C[idx] = v + bias[n] + res[idx];
                } else if (EPI == EPI_SILU) {
                    float zz = v + bias[n];
                    C[idx] = zz / (1.f + __expf(-zz));
                }
            }
        }
    }
}

// ---------------- edge_bias [b,q,k,h] -> g_s [b,h,q,k] ---------------------
__global__ void bias_transpose(const float* __restrict__ eb, float* __restrict__ s)
{
    int kc = blockIdx.x;
    int q  = blockIdx.y;
    int b  = blockIdx.z;
    __shared__ float t[64 * 17];
    size_t ibase = (((size_t)(b * 1024 + q)) * 1024 + kc * 64) * 16;
    for (int idx = threadIdx.x; idx < 1024; idx += 256)
        t[(idx >> 4) * 17 + (idx & 15)] = eb[ibase + idx];
    __syncthreads();
    for (int idx = threadIdx.x; idx < 1024; idx += 256) {
        int h = idx >> 6, kk = idx & 63;
        s[(((size_t)(b * 16 + h) * 1024 + q)) * 1024 + kc * 64 + kk] = t[kk * 17 + h];
    }
}

// ------- softmax over k; probs back to g_s and d_out [b,q,k,h] -------------
__global__ __launch_bounds__(512)
void softmax_kernel(float* __restrict__ s, float* __restrict__ attn_out)
{
    int q = blockIdx.x;
    int b = blockIdx.y;
    int w    = threadIdx.x >> 5;
    int lane = threadIdx.x & 31;
    float* row = s + (((size_t)(b * 16 + w) * 1024 + q)) * 1024;

    float v[32];
    float mx = -CUDART_INF_F;
#pragma unroll
    for (int i = 0; i < 32; i++) {
        v[i] = row[i * 32 + lane];
        mx = fmaxf(mx, v[i]);
    }
#pragma unroll
    for (int o = 16; o; o >>= 1) mx = fmaxf(mx, __shfl_xor_sync(0xffffffffu, mx, o));
    float sum = 0.f;
#pragma unroll
    for (int i = 0; i < 32; i++) { v[i] = __expf(v[i] - mx); sum += v[i]; }
#pragma unroll
    for (int o = 16; o; o >>= 1) sum += __shfl_xor_sync(0xffffffffu, sum, o);
    float inv = 1.f / sum;
#pragma unroll
    for (int i = 0; i < 32; i++) { v[i] *= inv; row[i * 32 + lane] = v[i]; }

    __shared__ float tile[16 * 513];
    float* out = attn_out + ((size_t)(b * 1024 + q)) * 16384;
#pragma unroll
    for (int half = 0; half < 2; half++) {
        __syncthreads();
#pragma unroll
        for (int i = 0; i < 16; i++) {
            int k = (half * 16 + i) * 32 + lane;
            tile[w * 513 + (k - half * 512)] = v[half * 16 + i];
        }
        __syncthreads();
        for (int idx = threadIdx.x; idx < 8192; idx += 512) {
            int k = idx >> 4, h = idx & 15;
            out[half * 8192 + idx] = tile[h * 513 + k];
        }
    }
}

// ---------------- row LayerNorm over D=1024 --------------------------------
__global__ __launch_bounds__(256)
void ln_kernel(const float* __restrict__ in, float* __restrict__ out,
               const float* __restrict__ gg, const float* __restrict__ bb)
{
    int row = blockIdx.x;
    int tid = threadIdx.x;
    float4 v = reinterpret_cast<const float4*>(in + (size_t)row * 1024)[tid];
    float s  = v.x + v.y + v.z + v.w;
    float ss = v.x * v.x + v.y * v.y + v.z * v.z + v.w * v.w;
#pragma unroll
    for (int o = 16; o; o >>= 1) {
        s  += __shfl_xor_sync(0xffffffffu, s, o);
        ss += __shfl_xor_sync(0xffffffffu, ss, o);
    }
    __shared__ float rs[8], rss[8];
    if ((tid & 31) == 0) { rs[tid >> 5] = s; rss[tid >> 5] = ss; }
    __syncthreads();
    if (tid < 32) {
        float a = (tid < 8) ? rs[tid] : 0.f;
        float c = (tid < 8) ? rss[tid] : 0.f;
#pragma unroll
        for (int o = 4; o; o >>= 1) {
            a += __shfl_xor_sync(0xffffffffu, a, o);
            c += __shfl_xor_sync(0xffffffffu, c, o);
        }
        if (tid == 0) { rs[0] = a; rss[0] = c; }
    }
    __syncthreads();
    float mean = rs[0] * (1.f / 1024.f);
    float var  = rss[0] * (1.f / 1024.f) - mean * mean;
    float inv  = rsqrtf(var + 1e-5f);
    float4 g4 = ((const float4*)gg)[tid];
    float4 b4 = ((const float4*)bb)[tid];
    float4 o4;
    o4.x = (v.x - mean) * inv * g4.x + b4.x;
    o4.y = (v.y - mean) * inv * g4.y + b4.y;
    o4.z = (v.z - mean) * inv * g4.z + b4.z;
    o4.w = (v.w - mean) * inv * g4.w + b4.w;
    reinterpret_cast<float4*>(out + (size_t)row * 1024)[tid] = o4;
}

// ---------------- launcher --------------------------------------------------
extern "C" void kernel_launch(void* const* d_in, const int* in_sizes, int n_in,
                              void* d_out, int out_size)
{
    const float* x    = (const float*)d_in[0];
    const float* eb   = (const float*)d_in[1];
    const unsigned char* mask = (const unsigned char*)d_in[2];
    const float* wq   = (const float*)d_in[3];
    const float* wk   = (const float*)d_in[4];
    const float* wv   = (const float*)d_in[5];
    const float* wo   = (const float*)d_in[6];
    const float* bo   = (const float*)d_in[7];
    const float* wg   = (const float*)d_in[8];
    const float* bg   = (const float*)d_in[9];
    const float* w1   = (const float*)d_in[10];
    const float* b1   = (const float*)d_in[11];
    const float* w2   = (const float*)d_in[12];
    const float* b2   = (const float*)d_in[13];
    const float* ln1g = (const float*)d_in[14];
    const float* ln1b = (const float*)d_in[15];
    const float* ln2g = (const float*)d_in[16];
    const float* ln2b = (const float*)d_in[17];

    float* out_x    = (float*)d_out;
    float* out_attn = (float*)d_out + (size_t)NTOK * 1024;

    float *q, *kt, *v, *g, *s, *o, *r1, *y, *u, *r2;
    cudaGetSymbolAddress((void**)&q,  g_q);
    cudaGetSymbolAddress((void**)&kt, g_kt);
    cudaGetSymbolAddress((void**)&v,  g_v);
    cudaGetSymbolAddress((void**)&g,  g_gate);
    cudaGetSymbolAddress((void**)&s,  g_s);
    cudaGetSymbolAddress((void**)&o,  g_o);
    cudaGetSymbolAddress((void**)&r1, g_r1);
    cudaGetSymbolAddress((void**)&y,  g_y);
    cudaGetSymbolAddress((void**)&u,  g_u);
    cudaGetSymbolAddress((void**)&r2, g_r2);

    dim3 blk(256);

    // 1) edge_bias -> g_s ([b,h,q,k])
    bias_transpose<<<dim3(16, 1024, 2), 256>>>(eb, s);

    // 2) projections (TF32 tensor cores)
    tgemm<EPI_SCALE><<<dim3(8, 16, 1), blk>>>(x, wq, q, NTOK, 1024, 1024, 1024, 1024, 1024,
        1, 0, 0, 0, 0, 0, 0, nullptr, nullptr, nullptr, QSCALE);
    tgemm<EPI_KT><<<dim3(8, 16, 1), blk>>>(x, wk, kt, NTOK, 1024, 1024, 1024, 1024, 1024,
        1, 0, 0, 0, 0, 0, 0, nullptr, nullptr, nullptr, 1.f);
    tgemm<EPI_SCALE><<<dim3(8, 16, 1), blk>>>(x, wv, v, NTOK, 1024, 1024, 1024, 1024, 1024,
        1, 0, 0, 0, 0, 0, 0, nullptr, nullptr, nullptr, 1.f);
    tgemm<EPI_SIGB><<<dim3(8, 16, 1), blk>>>(x, wg, g, NTOK, 1024, 1024, 1024, 1024, 1024,
        1, 0, 0, 0, 0, 0, 0, bg, nullptr, nullptr, 1.f);

    // 3) scores: per (b,h): Q_h @ Kt_h + bias (+mask) into g_s
    tgemm<EPI_BIASADD_MASK><<<dim3(8, 8, 32), blk>>>(q, kt, s, 1024, 1024, 64,
        1024, 1024, 1024,
        16,
        (long long)1048576, 64,
        (long long)1048576, 65536,
        (long long)16777216, 1048576,
        nullptr, nullptr, mask, 1.f);

    // 4) softmax
    softmax_kernel<<<dim3(1024, 2), 512>>>(s, out_attn);

    // 5) o = (probs @ V_h) * gate
    tgemm<EPI_GATE><<<dim3(1, 8, 32), blk>>>(s, v, o, 1024, 64, 1024,
        1024, 1024, 1024,
        16,
        (long long)16777216, 1048576,
        (long long)1048576, 64,
        (long long)1048576, 64,
        nullptr, g, nullptr, 1.f);

    // 6) delta = o @ wo + bo + x -> r1 ; LN1 -> y
    tgemm<EPI_RESBIAS><<<dim3(8, 16, 1), blk>>>(o, wo, r1, NTOK, 1024, 1024, 1024, 1024, 1024,
        1, 0, 0, 0, 0, 0, 0, bo, x, nullptr, 1.f);
    ln_kernel<<<NTOK, 256>>>(r1, y, ln1g, ln1b);

    // 7) FFN
    tgemm<EPI_SILU><<<dim3(16, 16, 1), blk>>>(y, w1, u, NTOK, FFN, 1024, 1024, FFN, FFN,
        1, 0, 0, 0, 0, 0, 0, b1, nullptr, nullptr, 1.f);
    tgemm<EPI_RESBIAS><<<dim3(8, 16, 1), blk>>>(u, w2, r2, NTOK, 1024, FFN, FFN, 1024, 1024,
        1, 0, 0, 0, 0, 0, 0, b2, y, nullptr, 1.f);
    ln_kernel<<<NTOK, 256>>>(r2, out_x, ln2g, ln2b);
}